// round 3
// baseline (speedup 1.0000x reference)
#include <cuda_runtime.h>

#define N_NODES 100000
#define E_EDGES 800000
#define H_HEADS 12
#define D_DIM 96
#define NH (N_NODES * H_HEADS)
#define LRELU_SLOPE 0.2f
#define SB 512                    // scan block size
#define NBLK ((N_NODES + SB - 1) / SB)   // 196

// ---------------- scratch (static device globals) ----------------------------
__device__ float4 g_s_src4[N_NODES * 3];   // [N,H] source scores
__device__ float4 g_s_trg4[N_NODES * 3];   // [N,H] target scores
__device__ float4 g_denom4[N_NODES * 3];   // [N,H] softmax denominators
__device__ float4 g_rden4 [N_NODES * 3];   // reciprocals
__device__ float4 g_exp4  [E_EDGES * 3];   // [E,H] exp(lrelu(score))
__device__ float  g_norm  [N_NODES * D_DIM]; // normalized aggregated rows
__device__ int    g_idx[2 * E_EDGES];      // normalized int32 edge index
__device__ int    g_cnt[N_NODES];          // in-degree
__device__ int    g_scanI[NBLK * SB];      // inclusive scan
__device__ int    g_part[NBLK];            // block partials
__device__ int    g_base[N_NODES];         // CSR row start
__device__ int    g_cursor[N_NODES];       // scatter cursors
__device__ int2   g_elist[E_EDGES];        // {src, edge_id} grouped by target
__device__ int    g_is64;

// ---------------- pass 0: dtype detect + index normalize ---------------------
__global__ void detect_kernel(const int* __restrict__ ei32) {
    if (threadIdx.x == 0) {
        int allz = 1;
        #pragma unroll
        for (int i = 1; i < 128; i += 2) allz &= (ei32[i] == 0);
        g_is64 = allz;
    }
}
__global__ void convert_kernel(const void* __restrict__ ei) {
    int i = blockIdx.x * blockDim.x + threadIdx.x;
    if (i >= 2 * E_EDGES) return;
    g_idx[i] = g_is64 ? (int)((const long long*)ei)[i] : ((const int*)ei)[i];
}

// ---------------- pass 1: node scores + zero denom/cnt -----------------------
__global__ void node_scores_kernel(const float* __restrict__ x,
                                   const float* __restrict__ score_src,
                                   const float* __restrict__ score_trg) {
    int idx = blockIdx.x * blockDim.x + threadIdx.x;   // n*12 + h
    if (idx >= NH) return;
    int h = idx % H_HEADS;

    const float4* xp = reinterpret_cast<const float4*>(x) + idx * 2;
    float4 xa = xp[0], xb = xp[1];
    const float4* sa = reinterpret_cast<const float4*>(score_src) + h * 2;
    const float4* ta = reinterpret_cast<const float4*>(score_trg) + h * 2;
    float4 s0 = sa[0], s1 = sa[1], t0 = ta[0], t1 = ta[1];

    float ssrc = xa.x*s0.x + xa.y*s0.y + xa.z*s0.z + xa.w*s0.w
               + xb.x*s1.x + xb.y*s1.y + xb.z*s1.z + xb.w*s1.w;
    float strg = xa.x*t0.x + xa.y*t0.y + xa.z*t0.z + xa.w*t0.w
               + xb.x*t1.x + xb.y*t1.y + xb.z*t1.z + xb.w*t1.w;

    reinterpret_cast<float*>(g_s_src4)[idx] = ssrc;
    reinterpret_cast<float*>(g_s_trg4)[idx] = strg;
    reinterpret_cast<float*>(g_denom4)[idx] = 0.0f;
    if (h == 0) g_cnt[idx / H_HEADS] = 0;
}

// ---------------- pass 2: exp scores + denom atomics + degree count ----------
__global__ void edge_denom_kernel() {
    int gid = blockIdx.x * blockDim.x + threadIdx.x;
    if (gid >= E_EDGES * 3) return;
    int e = gid / 3;
    int j = gid - e * 3;
    int src = g_idx[e];
    int trg = g_idx[E_EDGES + e];

    float4 a = g_s_src4[src * 3 + j];
    float4 b = g_s_trg4[trg * 3 + j];
    float4 v; float s;
    s = a.x + b.x; s = (s >= 0.f) ? s : LRELU_SLOPE * s; v.x = __expf(s);
    s = a.y + b.y; s = (s >= 0.f) ? s : LRELU_SLOPE * s; v.y = __expf(s);
    s = a.z + b.z; s = (s >= 0.f) ? s : LRELU_SLOPE * s; v.z = __expf(s);
    s = a.w + b.w; s = (s >= 0.f) ? s : LRELU_SLOPE * s; v.w = __expf(s);

    g_exp4[e * 3 + j] = v;
    atomicAdd(&g_denom4[trg * 3 + j], v);
    if (j == 0) atomicAdd(&g_cnt[trg], 1);
}

// ---------------- pass 2b: reciprocal denominators ----------------------------
__global__ void rdenom_kernel() {
    int i = blockIdx.x * blockDim.x + threadIdx.x;
    if (i >= N_NODES * 3) return;
    float4 d = g_denom4[i];
    float4 r;
    r.x = __fdividef(1.0f, d.x + 1e-16f);
    r.y = __fdividef(1.0f, d.y + 1e-16f);
    r.z = __fdividef(1.0f, d.z + 1e-16f);
    r.w = __fdividef(1.0f, d.w + 1e-16f);
    g_rden4[i] = r;
}

// ---------------- pass 3: exclusive scan of degrees (3 kernels) ---------------
__global__ void scan1_kernel() {
    __shared__ int s[SB];
    int t = threadIdx.x;
    int i = blockIdx.x * SB + t;
    int v = (i < N_NODES) ? g_cnt[i] : 0;
    s[t] = v;
    __syncthreads();
    #pragma unroll
    for (int off = 1; off < SB; off <<= 1) {
        int u = (t >= off) ? s[t - off] : 0;
        __syncthreads();
        s[t] += u;
        __syncthreads();
    }
    g_scanI[i] = s[t];
    if (t == SB - 1) g_part[blockIdx.x] = s[t];
}
__global__ void scan2_kernel() {
    if (threadIdx.x == 0) {
        int run = 0;
        for (int b = 0; b < NBLK; b++) { int t = g_part[b]; g_part[b] = run; run += t; }
    }
}
__global__ void scan3_kernel() {
    int i = blockIdx.x * SB + threadIdx.x;
    if (i >= N_NODES) return;
    int excl = g_scanI[i] - g_cnt[i] + g_part[i / SB];
    g_base[i] = excl;
    g_cursor[i] = excl;
}

// ---------------- pass 3c: scatter edges into target bins ---------------------
__global__ void scatter_kernel() {
    int e = blockIdx.x * blockDim.x + threadIdx.x;
    if (e >= E_EDGES) return;
    int src = g_idx[e];
    int trg = g_idx[E_EDGES + e];
    int pos = atomicAdd(&g_cursor[trg], 1);
    g_elist[pos] = make_int2(src, e);
}

// ---------------- pass 4: atomic-free aggregation + RMS norm ------------------
// one block (96 threads) per node; thread t owns feature element t (head t/8).
#define LCAP 128
__global__ __launch_bounds__(96) void agg_norm_kernel(
        const float* __restrict__ x,
        const float* __restrict__ lnw) {
    __shared__ int2  s_list[LCAP];
    __shared__ float s_rd[12];
    __shared__ float s_w[3];
    __shared__ float s_rms;

    int n = blockIdx.x;
    int t = threadIdx.x;
    int h = t >> 3;

    if (t < 12) s_rd[t] = reinterpret_cast<const float*>(g_rden4)[n * 12 + t];
    int base = g_base[n];
    int deg  = g_cnt[n];
    const float* expf_ = reinterpret_cast<const float*>(g_exp4);

    float acc = 0.0f;
    for (int tile = 0; tile < deg; tile += LCAP) {
        int cnt = min(LCAP, deg - tile);
        __syncthreads();
        for (int i = t; i < cnt; i += 96) s_list[i] = g_elist[base + tile + i];
        __syncthreads();
        for (int i = 0; i < cnt; i++) {
            int2 se = s_list[i];
            float a = expf_[se.y * 12 + h];
            acc += a * x[se.x * 96 + t];
        }
    }
    acc *= s_rd[h];

    // RMS over the 96-element row
    float ss = acc * acc;
    #pragma unroll
    for (int o = 16; o > 0; o >>= 1) ss += __shfl_down_sync(0xffffffffu, ss, o);
    if ((t & 31) == 0) s_w[t >> 5] = ss;
    __syncthreads();
    if (t == 0) s_rms = rsqrtf((s_w[0] + s_w[1] + s_w[2]) * (1.0f / 96.0f) + 1e-6f);
    __syncthreads();

    g_norm[n * 96 + t] = acc * s_rms * lnw[t];
}

// ---------------- pass 5: GEMM (out = x + norm @ W^T) ------------------------
__global__ __launch_bounds__(128) void gemm_kernel(
        const float* __restrict__ x,
        const float* __restrict__ wproj,
        float* __restrict__ out) {
    __shared__ float4 Wp[96][25];
    __shared__ float4 sm_n[16][25];

    int tid = threadIdx.x;
    int node0 = blockIdx.x * 16;

    const float4* w4 = reinterpret_cast<const float4*>(wproj);
    for (int i = tid; i < 96 * 24; i += 128) {
        int r = i / 24, c2 = i - r * 24;
        Wp[r][c2] = w4[i];
    }
    const float4* n4 = reinterpret_cast<const float4*>(g_norm);
    for (int i = tid; i < 16 * 24; i += 128) {
        int nd = i / 24, c2 = i - nd * 24;
        sm_n[nd][c2] = n4[(node0 + nd) * 24 + c2];
    }
    __syncthreads();

    int wp = tid >> 5, lane = tid & 31;
    float acc[4][3];
    #pragma unroll
    for (int a = 0; a < 4; a++)
        #pragma unroll
        for (int b = 0; b < 3; b++) acc[a][b] = 0.f;

    #pragma unroll 4
    for (int k = 0; k < 24; k++) {
        float4 w0 = Wp[lane][k];
        float4 w1 = Wp[lane + 32][k];
        float4 w2 = Wp[lane + 64][k];
        #pragma unroll
        for (int a = 0; a < 4; a++) {
            float4 nb = sm_n[wp * 4 + a][k];
            acc[a][0] += nb.x * w0.x + nb.y * w0.y + nb.z * w0.z + nb.w * w0.w;
            acc[a][1] += nb.x * w1.x + nb.y * w1.y + nb.z * w1.z + nb.w * w1.w;
            acc[a][2] += nb.x * w2.x + nb.y * w2.y + nb.z * w2.z + nb.w * w2.w;
        }
    }

    #pragma unroll
    for (int a = 0; a < 4; a++) {
        int n = node0 + wp * 4 + a;
        out[n * 96 + lane]      = x[n * 96 + lane]      + acc[a][0];
        out[n * 96 + lane + 32] = x[n * 96 + lane + 32] + acc[a][1];
        out[n * 96 + lane + 64] = x[n * 96 + lane + 64] + acc[a][2];
    }
}

// ---------------- launch ------------------------------------------------------
extern "C" void kernel_launch(void* const* d_in, const int* in_sizes, int n_in,
                              void* d_out, int out_size) {
    const float* x   = (const float*)d_in[0];
    const void*  ei  = d_in[1];
    const float* w   = (const float*)d_in[2];
    const float* ss  = (const float*)d_in[3];
    const float* st  = (const float*)d_in[4];
    const float* lnw = (const float*)d_in[5];
    float*       out = (float*)d_out;

    detect_kernel<<<1, 32>>>((const int*)ei);
    convert_kernel<<<(2 * E_EDGES + 255) / 256, 256>>>(ei);
    node_scores_kernel<<<(NH + 255) / 256, 256>>>(x, ss, st);
    edge_denom_kernel<<<(E_EDGES * 3 + 255) / 256, 256>>>();
    rdenom_kernel<<<(N_NODES * 3 + 255) / 256, 256>>>();
    scan1_kernel<<<NBLK, SB>>>();
    scan2_kernel<<<1, 32>>>();
    scan3_kernel<<<NBLK, SB>>>();
    scatter_kernel<<<(E_EDGES + 255) / 256, 256>>>();
    agg_norm_kernel<<<N_NODES, 96>>>(x, lnw);
    gemm_kernel<<<N_NODES / 16, 128>>>(x, w, out);
}

// round 4
// speedup vs baseline: 1.5569x; 1.5569x over previous
#include <cuda_runtime.h>

#define N_NODES 100000
#define E_EDGES 800000
#define H_HEADS 12
#define D_DIM 96
#define NH (N_NODES * H_HEADS)
#define LRELU_SLOPE 0.2f

// ---------------- scratch (static device globals; 16B-aligned types) ---------
__device__ float4 g_s_src4[N_NODES * 3];    // [N,H] source scores
__device__ float4 g_s_trg4[N_NODES * 3];    // [N,H] target scores
__device__ float4 g_denom4[N_NODES * 3];    // [N,H] softmax denominators
__device__ float4 g_rden4 [N_NODES * 3];    // reciprocal denominators
__device__ float4 g_exp4  [E_EDGES * 3];    // [E,H] exp(lrelu(score))
__device__ float4 g_agg[N_NODES * (D_DIM/4)];// [N,24] float4 accumulators
__device__ int    g_idx[2 * E_EDGES];       // normalized int32 edge index
__device__ int    g_is64;

// ---------------- pass 0: dtype detect + index normalize ---------------------
__global__ void detect_kernel(const int* __restrict__ ei32) {
    if (threadIdx.x == 0) {
        int allz = 1;
        #pragma unroll
        for (int i = 1; i < 128; i += 2) allz &= (ei32[i] == 0);
        g_is64 = allz;   // all high words zero -> int64 layout
    }
}
__global__ void convert_kernel(const void* __restrict__ ei) {
    int i = blockIdx.x * blockDim.x + threadIdx.x;
    if (i >= 2 * E_EDGES) return;
    g_idx[i] = g_is64 ? (int)((const long long*)ei)[i] : ((const int*)ei)[i];
}

// ---------------- pass 1: node scores + zero denom/agg -----------------------
__global__ void node_scores_kernel(const float* __restrict__ x,
                                   const float* __restrict__ score_src,
                                   const float* __restrict__ score_trg) {
    int idx = blockIdx.x * blockDim.x + threadIdx.x;   // n*12 + h
    if (idx >= NH) return;
    int h = idx % H_HEADS;

    const float4* xp = reinterpret_cast<const float4*>(x) + idx * 2;
    float4 xa = xp[0], xb = xp[1];
    const float4* sa = reinterpret_cast<const float4*>(score_src) + h * 2;
    const float4* ta = reinterpret_cast<const float4*>(score_trg) + h * 2;
    float4 s0 = sa[0], s1 = sa[1], t0 = ta[0], t1 = ta[1];

    float ssrc = xa.x*s0.x + xa.y*s0.y + xa.z*s0.z + xa.w*s0.w
               + xb.x*s1.x + xb.y*s1.y + xb.z*s1.z + xb.w*s1.w;
    float strg = xa.x*t0.x + xa.y*t0.y + xa.z*t0.z + xa.w*t0.w
               + xb.x*t1.x + xb.y*t1.y + xb.z*t1.z + xb.w*t1.w;

    reinterpret_cast<float*>(g_s_src4)[idx] = ssrc;
    reinterpret_cast<float*>(g_s_trg4)[idx] = strg;
    reinterpret_cast<float*>(g_denom4)[idx] = 0.0f;
    float4 z = make_float4(0.f, 0.f, 0.f, 0.f);
    g_agg[idx * 2]     = z;
    g_agg[idx * 2 + 1] = z;
}

// ---------------- pass 2: exp scores (stored) + denom atomics -----------------
// one thread per (edge, head-quad); 3 threads per edge
__global__ void edge_denom_kernel() {
    int gid = blockIdx.x * blockDim.x + threadIdx.x;
    if (gid >= E_EDGES * 3) return;
    int e = gid / 3;
    int j = gid - e * 3;
    int src = g_idx[e];
    int trg = g_idx[E_EDGES + e];

    float4 a = g_s_src4[src * 3 + j];
    float4 b = g_s_trg4[trg * 3 + j];
    float4 v; float s;
    s = a.x + b.x; s = (s >= 0.f) ? s : LRELU_SLOPE * s; v.x = __expf(s);
    s = a.y + b.y; s = (s >= 0.f) ? s : LRELU_SLOPE * s; v.y = __expf(s);
    s = a.z + b.z; s = (s >= 0.f) ? s : LRELU_SLOPE * s; v.z = __expf(s);
    s = a.w + b.w; s = (s >= 0.f) ? s : LRELU_SLOPE * s; v.w = __expf(s);

    g_exp4[e * 3 + j] = v;
    atomicAdd(&g_denom4[trg * 3 + j], v);
}

// ---------------- pass 2b: reciprocal denominators ---------------------------
__global__ void rdenom_kernel() {
    int i = blockIdx.x * blockDim.x + threadIdx.x;
    if (i >= N_NODES * 3) return;
    float4 d = g_denom4[i];
    float4 r;
    r.x = __fdividef(1.0f, d.x + 1e-16f);
    r.y = __fdividef(1.0f, d.y + 1e-16f);
    r.z = __fdividef(1.0f, d.z + 1e-16f);
    r.w = __fdividef(1.0f, d.w + 1e-16f);
    g_rden4[i] = r;
}

// ---------------- pass 3: weighted aggregation (no MUFU) ----------------------
// one thread per (edge, head); 12 threads per edge; 8 floats (2 float4) each.
// threads of an edge cover a contiguous 384B row of x[src] -> coalesced gather.
__global__ void edge_agg_kernel(const float4* __restrict__ x4) {
    int gid = blockIdx.x * blockDim.x + threadIdx.x;
    if (gid >= E_EDGES * 12) return;
    int e = gid / 12;
    int h = gid - e * 12;
    int src = g_idx[e];
    int trg = g_idx[E_EDGES + e];

    float attn = reinterpret_cast<const float*>(g_exp4)[e * 12 + h]
               * reinterpret_cast<const float*>(g_rden4)[trg * 12 + h];

    float4 xa = x4[src * 24 + h * 2];
    float4 xb = x4[src * 24 + h * 2 + 1];
    float4 wa = make_float4(xa.x * attn, xa.y * attn, xa.z * attn, xa.w * attn);
    float4 wb = make_float4(xb.x * attn, xb.y * attn, xb.z * attn, xb.w * attn);
    atomicAdd(&g_agg[trg * 24 + h * 2],     wa);
    atomicAdd(&g_agg[trg * 24 + h * 2 + 1], wb);
}

// ---------------- pass 4: RMS norm + GEMM (out = x + normed @ W^T) -----------
__global__ __launch_bounds__(128) void norm_gemm_kernel(
        const float* __restrict__ x,
        const float* __restrict__ wproj,
        const float* __restrict__ lnw,
        float* __restrict__ out) {
    __shared__ float4 Wp[96][25];
    __shared__ float4 sm_n[16][25];
    __shared__ float  sm_rms[16];

    int tid = threadIdx.x;
    int node0 = blockIdx.x * 16;

    const float4* w4 = reinterpret_cast<const float4*>(wproj);
    for (int i = tid; i < 96 * 24; i += 128) {
        int r = i / 24, c2 = i - r * 24;
        Wp[r][c2] = w4[i];
    }
    for (int i = tid; i < 16 * 24; i += 128) {
        int nd = i / 24, c2 = i - nd * 24;
        sm_n[nd][c2] = g_agg[(node0 + nd) * 24 + c2];
    }
    __syncthreads();

    {
        int nd = tid >> 3, part = tid & 7;
        float ssum = 0.f;
        #pragma unroll
        for (int j = 0; j < 3; j++) {
            float4 v = sm_n[nd][part * 3 + j];
            ssum += v.x * v.x + v.y * v.y + v.z * v.z + v.w * v.w;
        }
        ssum += __shfl_down_sync(0xffffffffu, ssum, 4);
        ssum += __shfl_down_sync(0xffffffffu, ssum, 2);
        ssum += __shfl_down_sync(0xffffffffu, ssum, 1);
        if (part == 0)
            sm_rms[nd] = rsqrtf(ssum * (1.0f / 96.0f) + 1e-6f);
    }
    __syncthreads();

    for (int i = tid; i < 16 * 24; i += 128) {
        int nd = i / 24, c2 = i - nd * 24;
        float r = sm_rms[nd];
        float4 v = sm_n[nd][c2];
        float4 lw = reinterpret_cast<const float4*>(lnw)[c2];
        v.x *= r * lw.x; v.y *= r * lw.y; v.z *= r * lw.z; v.w *= r * lw.w;
        sm_n[nd][c2] = v;
    }
    __syncthreads();

    int wp = tid >> 5, lane = tid & 31;
    float acc[4][3];
    #pragma unroll
    for (int a = 0; a < 4; a++)
        #pragma unroll
        for (int b = 0; b < 3; b++) acc[a][b] = 0.f;

    #pragma unroll 4
    for (int k = 0; k < 24; k++) {
        float4 w0 = Wp[lane][k];
        float4 w1 = Wp[lane + 32][k];
        float4 w2 = Wp[lane + 64][k];
        #pragma unroll
        for (int a = 0; a < 4; a++) {
            float4 nb = sm_n[wp * 4 + a][k];
            acc[a][0] += nb.x * w0.x + nb.y * w0.y + nb.z * w0.z + nb.w * w0.w;
            acc[a][1] += nb.x * w1.x + nb.y * w1.y + nb.z * w1.z + nb.w * w1.w;
            acc[a][2] += nb.x * w2.x + nb.y * w2.y + nb.z * w2.z + nb.w * w2.w;
        }
    }

    #pragma unroll
    for (int a = 0; a < 4; a++) {
        int n = node0 + wp * 4 + a;
        out[n * 96 + lane]      = x[n * 96 + lane]      + acc[a][0];
        out[n * 96 + lane + 32] = x[n * 96 + lane + 32] + acc[a][1];
        out[n * 96 + lane + 64] = x[n * 96 + lane + 64] + acc[a][2];
    }
}

// ---------------- launch ------------------------------------------------------
extern "C" void kernel_launch(void* const* d_in, const int* in_sizes, int n_in,
                              void* d_out, int out_size) {
    const float* x   = (const float*)d_in[0];
    const void*  ei  = d_in[1];
    const float* w   = (const float*)d_in[2];
    const float* ss  = (const float*)d_in[3];
    const float* st  = (const float*)d_in[4];
    const float* lnw = (const float*)d_in[5];
    float*       out = (float*)d_out;

    detect_kernel<<<1, 32>>>((const int*)ei);
    convert_kernel<<<(2 * E_EDGES + 255) / 256, 256>>>(ei);
    node_scores_kernel<<<(NH + 255) / 256, 256>>>(x, ss, st);
    edge_denom_kernel<<<(E_EDGES * 3 + 255) / 256, 256>>>();
    rdenom_kernel<<<(N_NODES * 3 + 255) / 256, 256>>>();
    edge_agg_kernel<<<(E_EDGES * 12 + 255) / 256, 256>>>(
        reinterpret_cast<const float4*>(x));
    norm_gemm_kernel<<<N_NODES / 16, 128>>>(x, w, lnw, out);
}

// round 5
// speedup vs baseline: 1.6180x; 1.0392x over previous
#include <cuda_runtime.h>

#define N_NODES 100000
#define E_EDGES 800000
#define H_HEADS 12
#define D_DIM 96
#define NH (N_NODES * H_HEADS)
#define LRELU_SLOPE 0.2f
#define SB 512
#define NBLK ((N_NODES + SB - 1) / SB)   // 196
#define SEG 8
#define NSEG ((E_EDGES + SEG - 1) / SEG) // 100000

// ---------------- scratch ------------------------------------------------------
__device__ float4 g_s_src4[N_NODES * 3];     // [N,H] source scores
__device__ float4 g_s_trg4[N_NODES * 3];     // [N,H] target scores
__device__ float4 g_exp4  [E_EDGES * 3];     // [E,H] exp(lrelu(score))
__device__ float4 g_agg[N_NODES * 24];       // [N,96] unnormalized accumulators
__device__ float  g_den[NH];                 // [N,H] denominators
__device__ int    g_idx[2 * E_EDGES];        // int32 edge index
__device__ int    g_cnt[N_NODES];            // in-degree
__device__ int    g_scanI[NBLK * SB];
__device__ int    g_part[NBLK];
__device__ int    g_base[N_NODES];
__device__ int    g_cursor[N_NODES];
__device__ int4   g_elist[E_EDGES];          // {src, e, trg, 0} sorted by trg
__device__ int    g_is64;

// ---------------- tiny setup kernels -------------------------------------------
__global__ void zero_cnt_kernel() {
    int i = blockIdx.x * blockDim.x + threadIdx.x;
    if (i < N_NODES) g_cnt[i] = 0;
}
__global__ void detect_kernel(const int* __restrict__ ei32) {
    if (threadIdx.x == 0) {
        int allz = 1;
        #pragma unroll
        for (int i = 1; i < 128; i += 2) allz &= (ei32[i] == 0);
        g_is64 = allz;
    }
}
// normalize index dtype + count in-degrees
__global__ void convert_kernel(const void* __restrict__ ei) {
    int i = blockIdx.x * blockDim.x + threadIdx.x;
    if (i >= 2 * E_EDGES) return;
    int v = g_is64 ? (int)((const long long*)ei)[i] : ((const int*)ei)[i];
    g_idx[i] = v;
    if (i >= E_EDGES) atomicAdd(&g_cnt[v], 1);
}

// ---------------- node scores + zero agg/den -----------------------------------
__global__ void node_scores_kernel(const float* __restrict__ x,
                                   const float* __restrict__ score_src,
                                   const float* __restrict__ score_trg) {
    int idx = blockIdx.x * blockDim.x + threadIdx.x;   // n*12 + h
    if (idx >= NH) return;
    int h = idx % H_HEADS;

    const float4* xp = reinterpret_cast<const float4*>(x) + idx * 2;
    float4 xa = xp[0], xb = xp[1];
    const float4* sa = reinterpret_cast<const float4*>(score_src) + h * 2;
    const float4* ta = reinterpret_cast<const float4*>(score_trg) + h * 2;
    float4 s0 = sa[0], s1 = sa[1], t0 = ta[0], t1 = ta[1];

    float ssrc = xa.x*s0.x + xa.y*s0.y + xa.z*s0.z + xa.w*s0.w
               + xb.x*s1.x + xb.y*s1.y + xb.z*s1.z + xb.w*s1.w;
    float strg = xa.x*t0.x + xa.y*t0.y + xa.z*t0.z + xa.w*t0.w
               + xb.x*t1.x + xb.y*t1.y + xb.z*t1.z + xb.w*t1.w;

    reinterpret_cast<float*>(g_s_src4)[idx] = ssrc;
    reinterpret_cast<float*>(g_s_trg4)[idx] = strg;
    g_den[idx] = 0.0f;
    float4 z = make_float4(0.f, 0.f, 0.f, 0.f);
    g_agg[idx * 2]     = z;
    g_agg[idx * 2 + 1] = z;
}

// ---------------- edge exp (streaming, NO atomics) ------------------------------
__global__ void edge_exp_kernel() {
    int gid = blockIdx.x * blockDim.x + threadIdx.x;
    if (gid >= E_EDGES * 3) return;
    int e = gid / 3;
    int j = gid - e * 3;
    int src = g_idx[e];
    int trg = g_idx[E_EDGES + e];

    float4 a = g_s_src4[src * 3 + j];
    float4 b = g_s_trg4[trg * 3 + j];
    float4 v; float s;
    s = a.x + b.x; s = (s >= 0.f) ? s : LRELU_SLOPE * s; v.x = __expf(s);
    s = a.y + b.y; s = (s >= 0.f) ? s : LRELU_SLOPE * s; v.y = __expf(s);
    s = a.z + b.z; s = (s >= 0.f) ? s : LRELU_SLOPE * s; v.z = __expf(s);
    s = a.w + b.w; s = (s >= 0.f) ? s : LRELU_SLOPE * s; v.w = __expf(s);
    g_exp4[e * 3 + j] = v;
}

// ---------------- degree scan (exclusive) ---------------------------------------
__global__ void scan1_kernel() {
    __shared__ int s[SB];
    int t = threadIdx.x;
    int i = blockIdx.x * SB + t;
    int v = (i < N_NODES) ? g_cnt[i] : 0;
    s[t] = v;
    __syncthreads();
    #pragma unroll
    for (int off = 1; off < SB; off <<= 1) {
        int u = (t >= off) ? s[t - off] : 0;
        __syncthreads();
        s[t] += u;
        __syncthreads();
    }
    g_scanI[i] = s[t];
    if (t == SB - 1) g_part[blockIdx.x] = s[t];
}
__global__ void scan2_kernel() {
    if (threadIdx.x == 0) {
        int run = 0;
        for (int b = 0; b < NBLK; b++) { int t = g_part[b]; g_part[b] = run; run += t; }
    }
}
__global__ void scan3_kernel() {
    int i = blockIdx.x * SB + threadIdx.x;
    if (i >= N_NODES) return;
    int excl = g_scanI[i] - g_cnt[i] + g_part[i / SB];
    g_base[i] = excl;
    g_cursor[i] = excl;
}

// ---------------- scatter edges into target-sorted list -------------------------
__global__ void scatter_kernel() {
    int e = blockIdx.x * blockDim.x + threadIdx.x;
    if (e >= E_EDGES) return;
    int src = g_idx[e];
    int trg = g_idx[E_EDGES + e];
    int pos = atomicAdd(&g_cursor[trg], 1);
    g_elist[pos] = make_int4(src, e, trg, 0);
}

// ---------------- sorted aggregation with register run-combining ---------------
// thread = (segment of SEG target-ordered edges, head h). Accumulates
// exp-weighted features + denom in registers, flushes atomics on trg change.
__global__ void sorted_agg_kernel(const float4* __restrict__ x4) {
    int gid = blockIdx.x * blockDim.x + threadIdx.x;
    if (gid >= NSEG * H_HEADS) return;
    int seg = gid / H_HEADS;
    int h   = gid - seg * H_HEADS;
    int p    = seg * SEG;
    int pend = min(p + SEG, E_EDGES);

    const float* expf_ = reinterpret_cast<const float*>(g_exp4);

    int cur = -1;
    float4 a = make_float4(0.f, 0.f, 0.f, 0.f);
    float4 b = make_float4(0.f, 0.f, 0.f, 0.f);
    float  d = 0.f;

    #pragma unroll
    for (int k = 0; k < SEG; k++, p++) {
        if (p >= pend) break;
        int4 se = g_elist[p];        // {src, e, trg, 0}
        if (se.z != cur) {
            if (cur >= 0) {
                atomicAdd(&g_agg[cur * 24 + h * 2],     a);
                atomicAdd(&g_agg[cur * 24 + h * 2 + 1], b);
                atomicAdd(&g_den[cur * 12 + h], d);
            }
            cur = se.z;
            a = make_float4(0.f, 0.f, 0.f, 0.f);
            b = make_float4(0.f, 0.f, 0.f, 0.f);
            d = 0.f;
        }
        float w = expf_[se.y * 12 + h];
        float4 xa = x4[se.x * 24 + h * 2];
        float4 xb = x4[se.x * 24 + h * 2 + 1];
        d += w;
        a.x += w * xa.x; a.y += w * xa.y; a.z += w * xa.z; a.w += w * xa.w;
        b.x += w * xb.x; b.y += w * xb.y; b.z += w * xb.z; b.w += w * xb.w;
    }
    if (cur >= 0) {
        atomicAdd(&g_agg[cur * 24 + h * 2],     a);
        atomicAdd(&g_agg[cur * 24 + h * 2 + 1], b);
        atomicAdd(&g_den[cur * 12 + h], d);
    }
}

// ---------------- normalize + RMS + GEMM (out = x + normed @ W^T) --------------
__global__ __launch_bounds__(128) void norm_gemm_kernel(
        const float* __restrict__ x,
        const float* __restrict__ wproj,
        const float* __restrict__ lnw,
        float* __restrict__ out) {
    __shared__ float4 Wp[96][25];
    __shared__ float4 sm_n[16][25];
    __shared__ float  sm_rd[16][12];
    __shared__ float  sm_rms[16];

    int tid = threadIdx.x;
    int node0 = blockIdx.x * 16;

    const float4* w4 = reinterpret_cast<const float4*>(wproj);
    for (int i = tid; i < 96 * 24; i += 128) {
        int r = i / 24, c2 = i - r * 24;
        Wp[r][c2] = w4[i];
    }
    for (int i = tid; i < 16 * 24; i += 128) {
        int nd = i / 24, c2 = i - nd * 24;
        sm_n[nd][c2] = g_agg[(node0 + nd) * 24 + c2];
    }
    // reciprocal denominators (16*12 = 192 values)
    for (int i = tid; i < 16 * 12; i += 128) {
        int nd = i / 12, h = i - nd * 12;
        sm_rd[nd][h] = __fdividef(1.0f, g_den[(node0 + nd) * 12 + h] + 1e-16f);
    }
    __syncthreads();

    // normalize (divide by denom), chunk c2 belongs to head c2/2
    for (int i = tid; i < 16 * 24; i += 128) {
        int nd = i / 24, c2 = i - nd * 24;
        float r = sm_rd[nd][c2 >> 1];
        float4 v = sm_n[nd][c2];
        v.x *= r; v.y *= r; v.z *= r; v.w *= r;
        sm_n[nd][c2] = v;
    }
    __syncthreads();

    // RMS: 8 threads per node
    {
        int nd = tid >> 3, part = tid & 7;
        float ssum = 0.f;
        #pragma unroll
        for (int j = 0; j < 3; j++) {
            float4 v = sm_n[nd][part * 3 + j];
            ssum += v.x * v.x + v.y * v.y + v.z * v.z + v.w * v.w;
        }
        ssum += __shfl_down_sync(0xffffffffu, ssum, 4);
        ssum += __shfl_down_sync(0xffffffffu, ssum, 2);
        ssum += __shfl_down_sync(0xffffffffu, ssum, 1);
        if (part == 0)
            sm_rms[nd] = rsqrtf(ssum * (1.0f / 96.0f) + 1e-6f);
    }
    __syncthreads();

    for (int i = tid; i < 16 * 24; i += 128) {
        int nd = i / 24, c2 = i - nd * 24;
        float r = sm_rms[nd];
        float4 v = sm_n[nd][c2];
        float4 lw = reinterpret_cast<const float4*>(lnw)[c2];
        v.x *= r * lw.x; v.y *= r * lw.y; v.z *= r * lw.z; v.w *= r * lw.w;
        sm_n[nd][c2] = v;
    }
    __syncthreads();

    int wp = tid >> 5, lane = tid & 31;
    float acc[4][3];
    #pragma unroll
    for (int aa = 0; aa < 4; aa++)
        #pragma unroll
        for (int bb = 0; bb < 3; bb++) acc[aa][bb] = 0.f;

    #pragma unroll 4
    for (int k = 0; k < 24; k++) {
        float4 w0 = Wp[lane][k];
        float4 w1 = Wp[lane + 32][k];
        float4 w2 = Wp[lane + 64][k];
        #pragma unroll
        for (int aa = 0; aa < 4; aa++) {
            float4 nb = sm_n[wp * 4 + aa][k];
            acc[aa][0] += nb.x * w0.x + nb.y * w0.y + nb.z * w0.z + nb.w * w0.w;
            acc[aa][1] += nb.x * w1.x + nb.y * w1.y + nb.z * w1.z + nb.w * w1.w;
            acc[aa][2] += nb.x * w2.x + nb.y * w2.y + nb.z * w2.z + nb.w * w2.w;
        }
    }

    #pragma unroll
    for (int aa = 0; aa < 4; aa++) {
        int n = node0 + wp * 4 + aa;
        out[n * 96 + lane]      = x[n * 96 + lane]      + acc[aa][0];
        out[n * 96 + lane + 32] = x[n * 96 + lane + 32] + acc[aa][1];
        out[n * 96 + lane + 64] = x[n * 96 + lane + 64] + acc[aa][2];
    }
}

// ---------------- launch ---------------------------------------------------------
extern "C" void kernel_launch(void* const* d_in, const int* in_sizes, int n_in,
                              void* d_out, int out_size) {
    const float* x   = (const float*)d_in[0];
    const void*  ei  = d_in[1];
    const float* w   = (const float*)d_in[2];
    const float* ss  = (const float*)d_in[3];
    const float* st  = (const float*)d_in[4];
    const float* lnw = (const float*)d_in[5];
    float*       out = (float*)d_out;

    zero_cnt_kernel<<<(N_NODES + 255) / 256, 256>>>();
    detect_kernel<<<1, 32>>>((const int*)ei);
    convert_kernel<<<(2 * E_EDGES + 255) / 256, 256>>>(ei);
    node_scores_kernel<<<(NH + 255) / 256, 256>>>(x, ss, st);
    edge_exp_kernel<<<(E_EDGES * 3 + 255) / 256, 256>>>();
    scan1_kernel<<<NBLK, SB>>>();
    scan2_kernel<<<1, 32>>>();
    scan3_kernel<<<NBLK, SB>>>();
    scatter_kernel<<<(E_EDGES + 255) / 256, 256>>>();
    sorted_agg_kernel<<<(NSEG * H_HEADS + 255) / 256, 256>>>(
        reinterpret_cast<const float4*>(x));
    norm_gemm_kernel<<<N_NODES / 16, 128>>>(x, w, lnw, out);
}

// round 6
// speedup vs baseline: 2.6031x; 1.6089x over previous
#include <cuda_runtime.h>

#define N_NODES 100000
#define E_EDGES 800000
#define H_HEADS 12
#define D_DIM 96
#define LRELU_SLOPE 0.2f
#define SB 512
#define NBLK ((N_NODES + SB - 1) / SB)   // 196

// ---------------- scratch ------------------------------------------------------
__device__ int    g_idx[2 * E_EDGES];     // int32 edge index (src | trg)
__device__ int    g_cnt[N_NODES];         // in-degree
__device__ int    g_scanI[NBLK * SB];     // inclusive block scans
__device__ int    g_part[NBLK];           // block partials (-> exclusive)
__device__ int    g_base[N_NODES];        // CSR row starts
__device__ int    g_cursor[N_NODES];      // scatter cursors
__device__ int    g_srcs[E_EDGES];        // source ids, grouped by target
__device__ float4 g_norm4[N_NODES * 24];  // normalized rows [N,96]
__device__ int    g_is64;

// ---------------- tiny setup ----------------------------------------------------
__global__ void zero_cnt_kernel() {
    int i = blockIdx.x * blockDim.x + threadIdx.x;
    if (i < N_NODES) g_cnt[i] = 0;
}
__global__ void detect_kernel(const int* __restrict__ ei32) {
    if (threadIdx.x == 0) {
        int allz = 1;
        #pragma unroll
        for (int i = 1; i < 128; i += 2) allz &= (ei32[i] == 0);
        g_is64 = allz;
    }
}
// dtype-normalize + count in-degrees
__global__ void convert_kernel(const void* __restrict__ ei) {
    int i = blockIdx.x * blockDim.x + threadIdx.x;
    if (i >= 2 * E_EDGES) return;
    int v = g_is64 ? (int)((const long long*)ei)[i] : ((const int*)ei)[i];
    g_idx[i] = v;
    if (i >= E_EDGES) atomicAdd(&g_cnt[v], 1);
}

// ---------------- degree scan ----------------------------------------------------
__global__ void scan1_kernel() {
    __shared__ int s[SB];
    int t = threadIdx.x;
    int i = blockIdx.x * SB + t;
    int v = (i < N_NODES) ? g_cnt[i] : 0;
    s[t] = v;
    __syncthreads();
    #pragma unroll
    for (int off = 1; off < SB; off <<= 1) {
        int u = (t >= off) ? s[t - off] : 0;
        __syncthreads();
        s[t] += u;
        __syncthreads();
    }
    g_scanI[i] = s[t];
    if (t == SB - 1) g_part[blockIdx.x] = s[t];
}
__global__ void scan2_kernel() {      // 1 block, 256 threads, NBLK=196 partials
    __shared__ int s[256];
    int t = threadIdx.x;
    int v = (t < NBLK) ? g_part[t] : 0;
    s[t] = v;
    __syncthreads();
    #pragma unroll
    for (int off = 1; off < 256; off <<= 1) {
        int u = (t >= off) ? s[t - off] : 0;
        __syncthreads();
        s[t] += u;
        __syncthreads();
    }
    if (t < NBLK) g_part[t] = s[t] - v;   // exclusive
}
__global__ void scan3_kernel() {
    int i = blockIdx.x * SB + threadIdx.x;
    if (i >= N_NODES) return;
    int excl = g_scanI[i] - g_cnt[i] + g_part[i / SB];
    g_base[i] = excl;
    g_cursor[i] = excl;
}

// ---------------- scatter: 4B per edge -------------------------------------------
__global__ void scatter_kernel() {
    int e = blockIdx.x * blockDim.x + threadIdx.x;
    if (e >= E_EDGES) return;
    int src = g_idx[e];
    int trg = g_idx[E_EDGES + e];
    int pos = atomicAdd(&g_cursor[trg], 1);
    g_srcs[pos] = src;
}

// ---------------- fused agg: score + exp + aggregate + normalize + RMS + ln ------
// thread group of 16 lanes per node (12 active, one per head). Lane h:
//   strg = dot(x[n,h,:], a_trg[h])  (loop-invariant)
//   per edge: load x[src,h,:] (coalesced 384B row across lanes), compute
//   s = strg + dot(x_src, a_src[h]), w = exp(lrelu(s)), accumulate w*x_src, w.
// Atomic-free; normalization + RMS + ln_weight fused; writes g_norm once.
__global__ __launch_bounds__(256) void agg_norm_kernel(
        const float4* __restrict__ x4,
        const float*  __restrict__ a_src,
        const float*  __restrict__ a_trg,
        const float*  __restrict__ lnw) {
    int gid = blockIdx.x * 256 + threadIdx.x;   // n*16 + h
    int n = gid >> 4;
    int h = gid & 15;
    bool act = (h < 12);

    float4 as0, as1;
    float strg = 0.0f;
    int base = 0, deg = 0;
    if (act) {
        as0 = reinterpret_cast<const float4*>(a_src)[h * 2];
        as1 = reinterpret_cast<const float4*>(a_src)[h * 2 + 1];
        float4 at0 = reinterpret_cast<const float4*>(a_trg)[h * 2];
        float4 at1 = reinterpret_cast<const float4*>(a_trg)[h * 2 + 1];
        float4 xn0 = x4[n * 24 + h * 2];
        float4 xn1 = x4[n * 24 + h * 2 + 1];
        strg = xn0.x*at0.x + xn0.y*at0.y + xn0.z*at0.z + xn0.w*at0.w
             + xn1.x*at1.x + xn1.y*at1.y + xn1.z*at1.z + xn1.w*at1.w;
        base = g_base[n];
        deg  = g_cnt[n];
    }

    float4 a = make_float4(0.f, 0.f, 0.f, 0.f);
    float4 b = make_float4(0.f, 0.f, 0.f, 0.f);
    float  d = 0.f;

    for (int i = 0; i < deg; i++) {
        int src = g_srcs[base + i];
        float4 xa = x4[src * 24 + h * 2];
        float4 xb = x4[src * 24 + h * 2 + 1];
        float s = strg
                + xa.x*as0.x + xa.y*as0.y + xa.z*as0.z + xa.w*as0.w
                + xb.x*as1.x + xb.y*as1.y + xb.z*as1.z + xb.w*as1.w;
        s = (s >= 0.f) ? s : LRELU_SLOPE * s;
        float w = __expf(s);
        d += w;
        a.x += w * xa.x; a.y += w * xa.y; a.z += w * xa.z; a.w += w * xa.w;
        b.x += w * xb.x; b.y += w * xb.y; b.z += w * xb.z; b.w += w * xb.w;
    }

    float r = __fdividef(1.0f, d + 1e-16f);
    a.x *= r; a.y *= r; a.z *= r; a.w *= r;
    b.x *= r; b.y *= r; b.z *= r; b.w *= r;

    // RMS across the node's 96 elements: reduce over the aligned 16-lane group
    float ss = act ? (a.x*a.x + a.y*a.y + a.z*a.z + a.w*a.w +
                      b.x*b.x + b.y*b.y + b.z*b.z + b.w*b.w) : 0.0f;
    ss += __shfl_xor_sync(0xffffffffu, ss, 8);
    ss += __shfl_xor_sync(0xffffffffu, ss, 4);
    ss += __shfl_xor_sync(0xffffffffu, ss, 2);
    ss += __shfl_xor_sync(0xffffffffu, ss, 1);
    float rms = rsqrtf(ss * (1.0f / 96.0f) + 1e-6f);

    if (act) {
        float4 l0 = reinterpret_cast<const float4*>(lnw)[h * 2];
        float4 l1 = reinterpret_cast<const float4*>(lnw)[h * 2 + 1];
        float4 o0 = make_float4(a.x*rms*l0.x, a.y*rms*l0.y, a.z*rms*l0.z, a.w*rms*l0.w);
        float4 o1 = make_float4(b.x*rms*l1.x, b.y*rms*l1.y, b.z*rms*l1.z, b.w*rms*l1.w);
        g_norm4[n * 24 + h * 2]     = o0;
        g_norm4[n * 24 + h * 2 + 1] = o1;
    }
}

// ---------------- GEMM: out = x + norm @ W^T (32 nodes / block) ------------------
__global__ __launch_bounds__(256) void gemm_kernel(
        const float* __restrict__ x,
        const float* __restrict__ wproj,
        float* __restrict__ out) {
    __shared__ float4 Wp[96][25];     // W row-major, padded
    __shared__ float4 sm_n[32][25];   // 32 node rows

    int tid = threadIdx.x;
    int node0 = blockIdx.x * 32;

    const float4* w4 = reinterpret_cast<const float4*>(wproj);
    for (int i = tid; i < 96 * 24; i += 256) {
        int r = i / 24, c2 = i - r * 24;
        Wp[r][c2] = w4[i];
    }
    for (int i = tid; i < 32 * 24; i += 256) {
        int nd = i / 24, c2 = i - nd * 24;
        sm_n[nd][c2] = g_norm4[(node0 + nd) * 24 + c2];
    }
    __syncthreads();

    int wp = tid >> 5, lane = tid & 31;   // 8 warps x 4 nodes
    float acc[4][3];
    #pragma unroll
    for (int aa = 0; aa < 4; aa++)
        #pragma unroll
        for (int bb = 0; bb < 3; bb++) acc[aa][bb] = 0.f;

    #pragma unroll 4
    for (int k = 0; k < 24; k++) {
        float4 w0 = Wp[lane][k];
        float4 w1 = Wp[lane + 32][k];
        float4 w2 = Wp[lane + 64][k];
        #pragma unroll
        for (int aa = 0; aa < 4; aa++) {
            float4 nb = sm_n[wp * 4 + aa][k];
            acc[aa][0] += nb.x * w0.x + nb.y * w0.y + nb.z * w0.z + nb.w * w0.w;
            acc[aa][1] += nb.x * w1.x + nb.y * w1.y + nb.z * w1.z + nb.w * w1.w;
            acc[aa][2] += nb.x * w2.x + nb.y * w2.y + nb.z * w2.z + nb.w * w2.w;
        }
    }

    #pragma unroll
    for (int aa = 0; aa < 4; aa++) {
        int n = node0 + wp * 4 + aa;
        out[n * 96 + lane]      = x[n * 96 + lane]      + acc[aa][0];
        out[n * 96 + lane + 32] = x[n * 96 + lane + 32] + acc[aa][1];
        out[n * 96 + lane + 64] = x[n * 96 + lane + 64] + acc[aa][2];
    }
}

// ---------------- launch -----------------------------------------------------------
extern "C" void kernel_launch(void* const* d_in, const int* in_sizes, int n_in,
                              void* d_out, int out_size) {
    const float* x   = (const float*)d_in[0];
    const void*  ei  = d_in[1];
    const float* w   = (const float*)d_in[2];
    const float* ss  = (const float*)d_in[3];
    const float* st  = (const float*)d_in[4];
    const float* lnw = (const float*)d_in[5];
    float*       out = (float*)d_out;

    zero_cnt_kernel<<<(N_NODES + 255) / 256, 256>>>();
    detect_kernel<<<1, 32>>>((const int*)ei);
    convert_kernel<<<(2 * E_EDGES + 255) / 256, 256>>>(ei);
    scan1_kernel<<<NBLK, SB>>>();
    scan2_kernel<<<1, 256>>>();
    scan3_kernel<<<NBLK, SB>>>();
    scatter_kernel<<<(E_EDGES + 255) / 256, 256>>>();
    agg_norm_kernel<<<(N_NODES * 16) / 256, 256>>>(
        reinterpret_cast<const float4*>(x), ss, st, lnw);
    gemm_kernel<<<N_NODES / 32, 256>>>(x, w, out);
}

// round 7
// speedup vs baseline: 2.6639x; 1.0233x over previous
#include <cuda_runtime.h>

#define N_NODES 100000
#define E_EDGES 800000
#define H_HEADS 12
#define D_DIM 96
#define LRELU_SLOPE 0.2f
#define SB 512
#define NBLK ((N_NODES + SB - 1) / SB)   // 196

// ---------------- scratch ------------------------------------------------------
__device__ int    g_idx[2 * E_EDGES];     // int32 edge index (src | trg)
__device__ int    g_cnt[N_NODES];         // in-degree
__device__ int    g_scanI[NBLK * SB];     // inclusive block scans
__device__ int    g_part[NBLK];           // block partials (-> exclusive)
__device__ int    g_base[N_NODES];        // CSR row starts
__device__ int    g_cursor[N_NODES];      // scatter cursors
__device__ int    g_srcs[E_EDGES];        // source ids, grouped by target
__device__ float4 g_norm4[N_NODES * 24];  // normalized rows [N,96]
__device__ int    g_is64;

// ---------------- setup: zero counts + dtype detect (merged) --------------------
__global__ void setup_kernel(const int* __restrict__ ei32) {
    int i = blockIdx.x * blockDim.x + threadIdx.x;
    if (i < N_NODES) g_cnt[i] = 0;
    if (i == 0) {
        int allz = 1;
        #pragma unroll
        for (int k = 1; k < 128; k += 2) allz &= (ei32[k] == 0);
        g_is64 = allz;
    }
}
// dtype-normalize + count in-degrees
__global__ void convert_kernel(const void* __restrict__ ei) {
    int i = blockIdx.x * blockDim.x + threadIdx.x;
    if (i >= 2 * E_EDGES) return;
    int v = g_is64 ? (int)((const long long*)ei)[i] : ((const int*)ei)[i];
    g_idx[i] = v;
    if (i >= E_EDGES) atomicAdd(&g_cnt[v], 1);
}

// ---------------- degree scan ----------------------------------------------------
__global__ void scan1_kernel() {
    __shared__ int s[SB];
    int t = threadIdx.x;
    int i = blockIdx.x * SB + t;
    int v = (i < N_NODES) ? g_cnt[i] : 0;
    s[t] = v;
    __syncthreads();
    #pragma unroll
    for (int off = 1; off < SB; off <<= 1) {
        int u = (t >= off) ? s[t - off] : 0;
        __syncthreads();
        s[t] += u;
        __syncthreads();
    }
    g_scanI[i] = s[t];
    if (t == SB - 1) g_part[blockIdx.x] = s[t];
}
__global__ void scan2_kernel() {
    __shared__ int s[256];
    int t = threadIdx.x;
    int v = (t < NBLK) ? g_part[t] : 0;
    s[t] = v;
    __syncthreads();
    #pragma unroll
    for (int off = 1; off < 256; off <<= 1) {
        int u = (t >= off) ? s[t - off] : 0;
        __syncthreads();
        s[t] += u;
        __syncthreads();
    }
    if (t < NBLK) g_part[t] = s[t] - v;   // exclusive
}
__global__ void scan3_kernel() {
    int i = blockIdx.x * SB + threadIdx.x;
    if (i >= N_NODES) return;
    int excl = g_scanI[i] - g_cnt[i] + g_part[i / SB];
    g_base[i] = excl;
    g_cursor[i] = excl;
}

// ---------------- scatter: 4B per edge -------------------------------------------
__global__ void scatter_kernel() {
    int e = blockIdx.x * blockDim.x + threadIdx.x;
    if (e >= E_EDGES) return;
    int src = g_idx[e];
    int trg = g_idx[E_EDGES + e];
    int pos = atomicAdd(&g_cursor[trg], 1);
    g_srcs[pos] = src;
}

// ---------------- fused agg (unroll-2): score+exp+agg+normalize+RMS+ln -----------
// 16 lanes per node (12 active, one per head). Edge loop unrolled by 2 so
// 4 independent LDG.128 are in flight per lane before consumption.
__global__ __launch_bounds__(256) void agg_norm_kernel(
        const float4* __restrict__ x4,
        const float*  __restrict__ a_src,
        const float*  __restrict__ a_trg,
        const float*  __restrict__ lnw) {
    int gid = blockIdx.x * 256 + threadIdx.x;   // n*16 + h
    int n = gid >> 4;
    int h = gid & 15;
    bool act = (h < 12);

    float4 as0, as1;
    float strg = 0.0f;
    int base = 0, deg = 0;
    if (act) {
        as0 = reinterpret_cast<const float4*>(a_src)[h * 2];
        as1 = reinterpret_cast<const float4*>(a_src)[h * 2 + 1];
        float4 at0 = reinterpret_cast<const float4*>(a_trg)[h * 2];
        float4 at1 = reinterpret_cast<const float4*>(a_trg)[h * 2 + 1];
        float4 xn0 = x4[n * 24 + h * 2];
        float4 xn1 = x4[n * 24 + h * 2 + 1];
        strg = xn0.x*at0.x + xn0.y*at0.y + xn0.z*at0.z + xn0.w*at0.w
             + xn1.x*at1.x + xn1.y*at1.y + xn1.z*at1.z + xn1.w*at1.w;
        base = g_base[n];
        deg  = g_cnt[n];
    }

    float4 a = make_float4(0.f, 0.f, 0.f, 0.f);
    float4 b = make_float4(0.f, 0.f, 0.f, 0.f);
    float  d = 0.f;

    int i = 0;
    for (; i + 2 <= deg; i += 2) {
        int s0 = g_srcs[base + i];
        int s1 = g_srcs[base + i + 1];
        float4 xa0 = x4[s0 * 24 + h * 2];
        float4 xb0 = x4[s0 * 24 + h * 2 + 1];
        float4 xa1 = x4[s1 * 24 + h * 2];
        float4 xb1 = x4[s1 * 24 + h * 2 + 1];

        float sc0 = strg
                  + xa0.x*as0.x + xa0.y*as0.y + xa0.z*as0.z + xa0.w*as0.w
                  + xb0.x*as1.x + xb0.y*as1.y + xb0.z*as1.z + xb0.w*as1.w;
        float sc1 = strg
                  + xa1.x*as0.x + xa1.y*as0.y + xa1.z*as0.z + xa1.w*as0.w
                  + xb1.x*as1.x + xb1.y*as1.y + xb1.z*as1.z + xb1.w*as1.w;
        sc0 = (sc0 >= 0.f) ? sc0 : LRELU_SLOPE * sc0;
        sc1 = (sc1 >= 0.f) ? sc1 : LRELU_SLOPE * sc1;
        float w0 = __expf(sc0);
        float w1 = __expf(sc1);

        d += w0 + w1;
        a.x += w0 * xa0.x + w1 * xa1.x;
        a.y += w0 * xa0.y + w1 * xa1.y;
        a.z += w0 * xa0.z + w1 * xa1.z;
        a.w += w0 * xa0.w + w1 * xa1.w;
        b.x += w0 * xb0.x + w1 * xb1.x;
        b.y += w0 * xb0.y + w1 * xb1.y;
        b.z += w0 * xb0.z + w1 * xb1.z;
        b.w += w0 * xb0.w + w1 * xb1.w;
    }
    if (i < deg) {
        int s0 = g_srcs[base + i];
        float4 xa0 = x4[s0 * 24 + h * 2];
        float4 xb0 = x4[s0 * 24 + h * 2 + 1];
        float sc0 = strg
                  + xa0.x*as0.x + xa0.y*as0.y + xa0.z*as0.z + xa0.w*as0.w
                  + xb0.x*as1.x + xb0.y*as1.y + xb0.z*as1.z + xb0.w*as1.w;
        sc0 = (sc0 >= 0.f) ? sc0 : LRELU_SLOPE * sc0;
        float w0 = __expf(sc0);
        d += w0;
        a.x += w0 * xa0.x; a.y += w0 * xa0.y; a.z += w0 * xa0.z; a.w += w0 * xa0.w;
        b.x += w0 * xb0.x; b.y += w0 * xb0.y; b.z += w0 * xb0.z; b.w += w0 * xb0.w;
    }

    float r = __fdividef(1.0f, d + 1e-16f);
    a.x *= r; a.y *= r; a.z *= r; a.w *= r;
    b.x *= r; b.y *= r; b.z *= r; b.w *= r;

    // RMS across the node's 96 elements (aligned 16-lane group)
    float ss = act ? (a.x*a.x + a.y*a.y + a.z*a.z + a.w*a.w +
                      b.x*b.x + b.y*b.y + b.z*b.z + b.w*b.w) : 0.0f;
    ss += __shfl_xor_sync(0xffffffffu, ss, 8);
    ss += __shfl_xor_sync(0xffffffffu, ss, 4);
    ss += __shfl_xor_sync(0xffffffffu, ss, 2);
    ss += __shfl_xor_sync(0xffffffffu, ss, 1);
    float rms = rsqrtf(ss * (1.0f / 96.0f) + 1e-6f);

    if (act) {
        float4 l0 = reinterpret_cast<const float4*>(lnw)[h * 2];
        float4 l1 = reinterpret_cast<const float4*>(lnw)[h * 2 + 1];
        float4 o0 = make_float4(a.x*rms*l0.x, a.y*rms*l0.y, a.z*rms*l0.z, a.w*rms*l0.w);
        float4 o1 = make_float4(b.x*rms*l1.x, b.y*rms*l1.y, b.z*rms*l1.z, b.w*rms*l1.w);
        g_norm4[n * 24 + h * 2]     = o0;
        g_norm4[n * 24 + h * 2 + 1] = o1;
    }
}

// ---------------- GEMM: out = x + norm @ W^T (64 nodes / block) ------------------
__global__ __launch_bounds__(256) void gemm_kernel(
        const float* __restrict__ x,
        const float* __restrict__ wproj,
        float* __restrict__ out) {
    __shared__ float4 Wp[96][25];     // 9.6KB
    __shared__ float4 sm_n[64][25];   // 25.6KB

    int tid = threadIdx.x;
    int node0 = blockIdx.x * 64;

    const float4* w4 = reinterpret_cast<const float4*>(wproj);
    for (int i = tid; i < 96 * 24; i += 256) {
        int r = i / 24, c2 = i - r * 24;
        Wp[r][c2] = w4[i];
    }
    for (int i = tid; i < 64 * 24; i += 256) {
        int nd = i / 24, c2 = i - nd * 24;
        sm_n[nd][c2] = g_norm4[(node0 + nd) * 24 + c2];
    }
    __syncthreads();

    int wp = tid >> 5, lane = tid & 31;   // 8 warps x 8 nodes each
    float acc[8][3];
    #pragma unroll
    for (int aa = 0; aa < 8; aa++)
        #pragma unroll
        for (int bb = 0; bb < 3; bb++) acc[aa][bb] = 0.f;

    #pragma unroll 2
    for (int k = 0; k < 24; k++) {
        float4 w0 = Wp[lane][k];
        float4 w1 = Wp[lane + 32][k];
        float4 w2 = Wp[lane + 64][k];
        #pragma unroll
        for (int aa = 0; aa < 8; aa++) {
            float4 nb = sm_n[wp * 8 + aa][k];
            acc[aa][0] += nb.x * w0.x + nb.y * w0.y + nb.z * w0.z + nb.w * w0.w;
            acc[aa][1] += nb.x * w1.x + nb.y * w1.y + nb.z * w1.z + nb.w * w1.w;
            acc[aa][2] += nb.x * w2.x + nb.y * w2.y + nb.z * w2.z + nb.w * w2.w;
        }
    }

    #pragma unroll
    for (int aa = 0; aa < 8; aa++) {
        int n = node0 + wp * 8 + aa;
        out[n * 96 + lane]      = x[n * 96 + lane]      + acc[aa][0];
        out[n * 96 + lane + 32] = x[n * 96 + lane + 32] + acc[aa][1];
        out[n * 96 + lane + 64] = x[n * 96 + lane + 64] + acc[aa][2];
    }
}

// ---------------- launch -----------------------------------------------------------
extern "C" void kernel_launch(void* const* d_in, const int* in_sizes, int n_in,
                              void* d_out, int out_size) {
    const float* x   = (const float*)d_in[0];
    const void*  ei  = d_in[1];
    const float* w   = (const float*)d_in[2];
    const float* ss  = (const float*)d_in[3];
    const float* st  = (const float*)d_in[4];
    const float* lnw = (const float*)d_in[5];
    float*       out = (float*)d_out;

    setup_kernel<<<(N_NODES + 255) / 256, 256>>>((const int*)ei);
    convert_kernel<<<(2 * E_EDGES + 255) / 256, 256>>>(ei);
    scan1_kernel<<<NBLK, SB>>>();
    scan2_kernel<<<1, 256>>>();
    scan3_kernel<<<NBLK, SB>>>();
    scatter_kernel<<<(E_EDGES + 255) / 256, 256>>>();
    agg_norm_kernel<<<(N_NODES * 16) / 256, 256>>>(
        reinterpret_cast<const float4*>(x), ss, st, lnw);
    gemm_kernel<<<(N_NODES + 63) / 64, 256>>>(x, w, out);
}

// round 8
// speedup vs baseline: 2.7047x; 1.0153x over previous
#include <cuda_runtime.h>

#define N_NODES 100000
#define E_EDGES 800000
#define H_HEADS 12
#define D_DIM 96
#define LRELU_SLOPE 0.2f

// ---------------- scratch ------------------------------------------------------
__device__ int    g_idx[2 * E_EDGES];     // int32 edge index (src | trg)
__device__ int    g_cnt[N_NODES];         // in-degree
__device__ int    g_base[N_NODES];        // CSR row starts
__device__ int    g_cursor[N_NODES];      // scatter cursors
__device__ int    g_srcs[E_EDGES];        // source ids, grouped by target
__device__ float4 g_norm4[N_NODES * 24];  // normalized rows [N,96]
__device__ int    g_total;                // running base counter
__device__ int    g_is64;

// ---------------- f32x2 helpers (Blackwell packed fp32 FMA) ---------------------
__device__ __forceinline__ void fma2(long long& d, long long a, long long b) {
    asm("fma.rn.f32x2 %0, %1, %2, %0;" : "+l"(d) : "l"(a), "l"(b));
}
__device__ __forceinline__ float2 upk(long long v) {
    float2 f;
    asm("mov.b64 {%0, %1}, %2;" : "=f"(f.x), "=f"(f.y) : "l"(v));
    return f;
}

// ---------------- setup: zero counts/total + dtype detect ------------------------
__global__ void setup_kernel(const int* __restrict__ ei32) {
    int i = blockIdx.x * blockDim.x + threadIdx.x;
    if (i < N_NODES) g_cnt[i] = 0;
    if (i == 0) {
        g_total = 0;
        int allz = 1;
        #pragma unroll
        for (int k = 1; k < 128; k += 2) allz &= (ei32[k] == 0);
        g_is64 = allz;
    }
}
// dtype-normalize + count in-degrees
__global__ void convert_kernel(const void* __restrict__ ei) {
    int i = blockIdx.x * blockDim.x + threadIdx.x;
    if (i >= 2 * E_EDGES) return;
    int v = g_is64 ? (int)((const long long*)ei)[i] : ((const int*)ei)[i];
    g_idx[i] = v;
    if (i >= E_EDGES) atomicAdd(&g_cnt[v], 1);
}

// ---------------- base assignment: warp scan + one atomic per warp ---------------
__global__ void base_kernel() {
    int i = blockIdx.x * blockDim.x + threadIdx.x;
    int lane = threadIdx.x & 31;
    int c = (i < N_NODES) ? g_cnt[i] : 0;

    // inclusive warp scan
    int pre = c;
    #pragma unroll
    for (int off = 1; off < 32; off <<= 1) {
        int u = __shfl_up_sync(0xffffffffu, pre, off);
        if (lane >= off) pre += u;
    }
    int tot = __shfl_sync(0xffffffffu, pre, 31);
    int excl = pre - c;

    int wb = 0;
    if (lane == 0) wb = atomicAdd(&g_total, tot);
    wb = __shfl_sync(0xffffffffu, wb, 0);

    if (i < N_NODES) {
        int b = wb + excl;
        g_base[i] = b;
        g_cursor[i] = b;
    }
}

// ---------------- scatter: 4B per edge -------------------------------------------
__global__ void scatter_kernel() {
    int e = blockIdx.x * blockDim.x + threadIdx.x;
    if (e >= E_EDGES) return;
    int src = g_idx[e];
    int trg = g_idx[E_EDGES + e];
    int pos = atomicAdd(&g_cursor[trg], 1);
    g_srcs[pos] = src;
}

// ---------------- fused agg (unroll-2): score+exp+agg+normalize+RMS+ln -----------
__global__ __launch_bounds__(256) void agg_norm_kernel(
        const float4* __restrict__ x4,
        const float*  __restrict__ a_src,
        const float*  __restrict__ a_trg,
        const float*  __restrict__ lnw) {
    int gid = blockIdx.x * 256 + threadIdx.x;   // n*16 + h
    int n = gid >> 4;
    int h = gid & 15;
    bool act = (h < 12);

    float4 as0, as1;
    float strg = 0.0f;
    int base = 0, deg = 0;
    if (act) {
        as0 = reinterpret_cast<const float4*>(a_src)[h * 2];
        as1 = reinterpret_cast<const float4*>(a_src)[h * 2 + 1];
        float4 at0 = reinterpret_cast<const float4*>(a_trg)[h * 2];
        float4 at1 = reinterpret_cast<const float4*>(a_trg)[h * 2 + 1];
        float4 xn0 = x4[n * 24 + h * 2];
        float4 xn1 = x4[n * 24 + h * 2 + 1];
        strg = xn0.x*at0.x + xn0.y*at0.y + xn0.z*at0.z + xn0.w*at0.w
             + xn1.x*at1.x + xn1.y*at1.y + xn1.z*at1.z + xn1.w*at1.w;
        base = g_base[n];
        deg  = g_cnt[n];
    }

    float4 a = make_float4(0.f, 0.f, 0.f, 0.f);
    float4 b = make_float4(0.f, 0.f, 0.f, 0.f);
    float  d = 0.f;

    int i = 0;
    for (; i + 2 <= deg; i += 2) {
        int s0 = g_srcs[base + i];
        int s1 = g_srcs[base + i + 1];
        float4 xa0 = x4[s0 * 24 + h * 2];
        float4 xb0 = x4[s0 * 24 + h * 2 + 1];
        float4 xa1 = x4[s1 * 24 + h * 2];
        float4 xb1 = x4[s1 * 24 + h * 2 + 1];

        float sc0 = strg
                  + xa0.x*as0.x + xa0.y*as0.y + xa0.z*as0.z + xa0.w*as0.w
                  + xb0.x*as1.x + xb0.y*as1.y + xb0.z*as1.z + xb0.w*as1.w;
        float sc1 = strg
                  + xa1.x*as0.x + xa1.y*as0.y + xa1.z*as0.z + xa1.w*as0.w
                  + xb1.x*as1.x + xb1.y*as1.y + xb1.z*as1.z + xb1.w*as1.w;
        sc0 = (sc0 >= 0.f) ? sc0 : LRELU_SLOPE * sc0;
        sc1 = (sc1 >= 0.f) ? sc1 : LRELU_SLOPE * sc1;
        float w0 = __expf(sc0);
        float w1 = __expf(sc1);

        d += w0 + w1;
        a.x += w0 * xa0.x + w1 * xa1.x;
        a.y += w0 * xa0.y + w1 * xa1.y;
        a.z += w0 * xa0.z + w1 * xa1.z;
        a.w += w0 * xa0.w + w1 * xa1.w;
        b.x += w0 * xb0.x + w1 * xb1.x;
        b.y += w0 * xb0.y + w1 * xb1.y;
        b.z += w0 * xb0.z + w1 * xb1.z;
        b.w += w0 * xb0.w + w1 * xb1.w;
    }
    if (i < deg) {
        int s0 = g_srcs[base + i];
        float4 xa0 = x4[s0 * 24 + h * 2];
        float4 xb0 = x4[s0 * 24 + h * 2 + 1];
        float sc0 = strg
                  + xa0.x*as0.x + xa0.y*as0.y + xa0.z*as0.z + xa0.w*as0.w
                  + xb0.x*as1.x + xb0.y*as1.y + xb0.z*as1.z + xb0.w*as1.w;
        sc0 = (sc0 >= 0.f) ? sc0 : LRELU_SLOPE * sc0;
        float w0 = __expf(sc0);
        d += w0;
        a.x += w0 * xa0.x; a.y += w0 * xa0.y; a.z += w0 * xa0.z; a.w += w0 * xa0.w;
        b.x += w0 * xb0.x; b.y += w0 * xb0.y; b.z += w0 * xb0.z; b.w += w0 * xb0.w;
    }

    float r = __fdividef(1.0f, d + 1e-16f);
    a.x *= r; a.y *= r; a.z *= r; a.w *= r;
    b.x *= r; b.y *= r; b.z *= r; b.w *= r;

    float ss = act ? (a.x*a.x + a.y*a.y + a.z*a.z + a.w*a.w +
                      b.x*b.x + b.y*b.y + b.z*b.z + b.w*b.w) : 0.0f;
    ss += __shfl_xor_sync(0xffffffffu, ss, 8);
    ss += __shfl_xor_sync(0xffffffffu, ss, 4);
    ss += __shfl_xor_sync(0xffffffffu, ss, 2);
    ss += __shfl_xor_sync(0xffffffffu, ss, 1);
    float rms = rsqrtf(ss * (1.0f / 96.0f) + 1e-6f);

    if (act) {
        float4 l0 = reinterpret_cast<const float4*>(lnw)[h * 2];
        float4 l1 = reinterpret_cast<const float4*>(lnw)[h * 2 + 1];
        float4 o0 = make_float4(a.x*rms*l0.x, a.y*rms*l0.y, a.z*rms*l0.z, a.w*rms*l0.w);
        float4 o1 = make_float4(b.x*rms*l1.x, b.y*rms*l1.y, b.z*rms*l1.z, b.w*rms*l1.w);
        g_norm4[n * 24 + h * 2]     = o0;
        g_norm4[n * 24 + h * 2 + 1] = o1;
    }
}

// ---------------- GEMM via f32x2: out = x + norm @ W^T (64 nodes / block) --------
__global__ __launch_bounds__(256) void gemm_kernel(
        const float* __restrict__ x,
        const float* __restrict__ wproj,
        float* __restrict__ out) {
    __shared__ float4 Wp[96][25];     // 9.6KB (pad avoids conflicts)
    __shared__ float4 sm_n[64][25];   // 25.6KB

    int tid = threadIdx.x;
    int node0 = blockIdx.x * 64;

    const float4* w4 = reinterpret_cast<const float4*>(wproj);
    for (int i = tid; i < 96 * 24; i += 256) {
        int r = i / 24, c2 = i - r * 24;
        Wp[r][c2] = w4[i];
    }
    for (int i = tid; i < 64 * 24; i += 256) {
        int nd = i / 24, c2 = i - nd * 24;
        sm_n[nd][c2] = g_norm4[(node0 + nd) * 24 + c2];
    }
    __syncthreads();

    int wp = tid >> 5, lane = tid & 31;   // 8 warps x 8 nodes each
    long long acc2[8][3];                  // packed f32x2 accumulators
    #pragma unroll
    for (int aa = 0; aa < 8; aa++)
        #pragma unroll
        for (int bb = 0; bb < 3; bb++) acc2[aa][bb] = 0LL;

    #pragma unroll 2
    for (int k = 0; k < 24; k++) {
        // read float4 smem as two f32x2 carriers (no repack MOVs)
        longlong2 w0 = *reinterpret_cast<const longlong2*>(&Wp[lane][k]);
        longlong2 w1 = *reinterpret_cast<const longlong2*>(&Wp[lane + 32][k]);
        longlong2 w2 = *reinterpret_cast<const longlong2*>(&Wp[lane + 64][k]);
        #pragma unroll
        for (int aa = 0; aa < 8; aa++) {
            longlong2 nb = *reinterpret_cast<const longlong2*>(&sm_n[wp * 8 + aa][k]);
            fma2(acc2[aa][0], nb.x, w0.x); fma2(acc2[aa][0], nb.y, w0.y);
            fma2(acc2[aa][1], nb.x, w1.x); fma2(acc2[aa][1], nb.y, w1.y);
            fma2(acc2[aa][2], nb.x, w2.x); fma2(acc2[aa][2], nb.y, w2.y);
        }
    }

    #pragma unroll
    for (int aa = 0; aa < 8; aa++) {
        int n = node0 + wp * 8 + aa;
        float2 p0 = upk(acc2[aa][0]);
        float2 p1 = upk(acc2[aa][1]);
        float2 p2 = upk(acc2[aa][2]);
        out[n * 96 + lane]      = x[n * 96 + lane]      + (p0.x + p0.y);
        out[n * 96 + lane + 32] = x[n * 96 + lane + 32] + (p1.x + p1.y);
        out[n * 96 + lane + 64] = x[n * 96 + lane + 64] + (p2.x + p2.y);
    }
}

// ---------------- launch -----------------------------------------------------------
extern "C" void kernel_launch(void* const* d_in, const int* in_sizes, int n_in,
                              void* d_out, int out_size) {
    const float* x   = (const float*)d_in[0];
    const void*  ei  = d_in[1];
    const float* w   = (const float*)d_in[2];
    const float* ss  = (const float*)d_in[3];
    const float* st  = (const float*)d_in[4];
    const float* lnw = (const float*)d_in[5];
    float*       out = (float*)d_out;

    setup_kernel<<<(N_NODES + 255) / 256, 256>>>((const int*)ei);
    convert_kernel<<<(2 * E_EDGES + 255) / 256, 256>>>(ei);
    base_kernel<<<(N_NODES + 255) / 256, 256>>>();
    scatter_kernel<<<(E_EDGES + 255) / 256, 256>>>();
    agg_norm_kernel<<<(N_NODES * 16) / 256, 256>>>(
        reinterpret_cast<const float4*>(x), ss, st, lnw);
    gemm_kernel<<<(N_NODES + 63) / 64, 256>>>(x, w, out);
}